// round 14
// baseline (speedup 1.0000x reference)
#include <cuda_runtime.h>
#include <cstdint>
#include <math.h>

#define NN 8746
#define KD 8746
#define HD 32
#define ZD 16
#define TT 6
#define EE 100000

// GEMM tiling: BM=128, BK=32, split-K x6 (grid 414, 3 blocks/SM), 3-stage
// pipeline, x/W tiles loaded via cp.async.bulk (TMA path) + mbarrier.
#define BMg 128
#define BKg 32
#define STg 3
#define KSPLIT 6
#define TPC 46
#define NTILE_TOT 274
#define XSTR 36                          // smem row stride in floats (144B)
#define XROWB (XSTR * 4)                 // 144
#define XTILE_BYTES (BMg * XROWB)        // 18432
#define WTILE_WORDS (BKg * HD)           // 1024
#define WTILE_BYTES (WTILE_WORDS * 4)    // 4096
#define STAGE_BYTES (XTILE_BYTES + WTILE_BYTES)   // 22528
#define GEMM_SMEM (STg * STAGE_BYTES)    // 67584

#define SCH 9

// ---------------- scratch (device globals; no allocations allowed) ----------
__device__ float    d_h0[NN * HD];
__device__ uint32_t d_w1t[NTILE_TOT * WTILE_WORDS];
__device__ float    d_xtail[NN * XSTR];        // last k-tile, pre-shifted + padded
__device__ int      d_cnt[TT * NN];
__device__ int      d_off[TT * (NN + 1)];
__device__ int      d_cur[TT * NN];
__device__ unsigned long long d_se[TT * EE];   // packed (eid<<32)|src
__device__ float    d_wb[TT * EE];
__device__ float    d_diag[TT * NN];
__device__ float    d_dinv[TT * NN];
__device__ float    d_g[TT * NN * ZD];

// ---------------- helpers ---------------------------------------------------
__device__ __forceinline__ uint32_t f2tf(float f) {
    uint32_t r;
    asm("cvt.rna.tf32.f32 %0, %1;" : "=r"(r) : "f"(f));
    return r;
}
__device__ __forceinline__ int ld_idx(const int* ei, int pos, int f) {
    return f ? ei[2 * pos] : ei[pos];
}
__device__ __forceinline__ int i64_flag(const int* ei) {
    return ((ei[1] | ei[3] | ei[5] | ei[7] | ei[9]) == 0) ? 1 : 0;
}
__device__ __forceinline__ uint32_t smem_u32(const void* p) {
    return (uint32_t)__cvta_generic_to_shared(p);
}
__device__ __forceinline__ void bulk_g2s(uint32_t dst, const void* src, int nb,
                                         uint32_t mbar) {
    asm volatile(
        "cp.async.bulk.shared::cta.global.mbarrier::complete_tx::bytes "
        "[%0], [%1], %2, [%3];\n"
        :: "r"(dst), "l"(src), "r"(nb), "r"(mbar) : "memory");
}
__device__ __forceinline__ void mbar_init(uint32_t mbar, uint32_t cnt) {
    asm volatile("mbarrier.init.shared.b64 [%0], %1;" :: "r"(mbar), "r"(cnt) : "memory");
}
__device__ __forceinline__ void mbar_expect(uint32_t mbar, uint32_t bytes) {
    asm volatile("mbarrier.arrive.expect_tx.shared.b64 _, [%0], %1;"
                 :: "r"(mbar), "r"(bytes) : "memory");
}
__device__ __forceinline__ void mbar_wait(uint32_t mbar, uint32_t parity) {
    uint32_t done;
    asm volatile(
        "{\n\t.reg .pred p;\n\t"
        "mbarrier.try_wait.parity.acquire.cta.shared::cta.b64 p, [%1], %2;\n\t"
        "selp.b32 %0, 1, 0, p;\n\t}"
        : "=r"(done) : "r"(mbar), "r"(parity) : "memory");
    if (!done) {
        asm volatile(
            "{\n\t.reg .pred P1;\n\t"
            "WL_%=:\n\t"
            "mbarrier.try_wait.parity.acquire.cta.shared::cta.b64 P1, [%0], %1, 0x989680;\n\t"
            "@P1 bra.uni WD_%=;\n\t"
            "bra.uni WL_%=;\n\t"
            "WD_%=:\n\t}"
            :: "r"(mbar), "r"(parity) : "memory");
    }
}

// ---------------- fused prep: zero h0/cnt + W1->tf32 + xtail staging ---------
#define PREP_H0 (NN * HD)
#define PREP_CNT (TT * NN)
#define PREP_W1 (NTILE_TOT * WTILE_WORDS)
#define PREP_XT (NN * XSTR)
#define PREP_TOT (PREP_H0 + PREP_CNT + PREP_W1 + PREP_XT)
#define KTAIL0 (273 * BKg)                      // 8736; KD-KTAIL0 = 10 valid cols
__global__ void prep_kernel(const float* __restrict__ W1, const float* __restrict__ x) {
    int idx = blockIdx.x * 256 + threadIdx.x;
    if (idx < PREP_H0) {
        d_h0[idx] = 0.f;
    } else if (idx < PREP_H0 + PREP_CNT) {
        d_cnt[idx - PREP_H0] = 0;
    } else if (idx < PREP_H0 + PREP_CNT + PREP_W1) {
        int w = idx - PREP_H0 - PREP_CNT;
        int kt = w >> 10, r = w & 1023;
        int s = r >> 8, r2 = r & 255;
        int half = (r2 >> 7) & 1;
        int l = (r2 >> 2) & 31;
        int j = r2 & 3;
        int k = kt * 32 + s * 8 + (l & 3) + half * 4;
        int n = (l >> 2) + j * 8;
        d_w1t[w] = (k < KD) ? f2tf(W1[k * HD + n]) : 0u;
    } else if (idx < PREP_TOT) {
        int w = idx - PREP_H0 - PREP_CNT - PREP_W1;
        int r = w / XSTR, c = w - r * XSTR;
        int sh = (r & 1) * 2;
        int kc = c - sh;
        float v = (kc >= 0 && kc < KD - KTAIL0) ? x[(size_t)r * KD + KTAIL0 + kc] : 0.f;
        d_xtail[w] = v;
    }
}

// ---------------- edge histogram --------------------------------------------
__global__ void hist_kernel(const int* __restrict__ ei) {
    int idx = blockIdx.x * 256 + threadIdx.x;
    if (idx >= TT * EE) return;
    int f = i64_flag(ei);
    int t = idx / EE, e = idx - t * EE;
    int j = ld_idx(ei, t * 2 * EE + EE + e, f);
    atomicAdd(&d_cnt[t * NN + j], 1);
}

// ---------------- scan: redundant prefix -------------------------------------
__global__ void __launch_bounds__(1024) scan_kernel() {
    const int t   = blockIdx.y;
    const int ch  = blockIdx.x;
    const int tid = threadIdx.x;
    const int lane = tid & 31, w = tid >> 5;
    __shared__ int wsum[32];
    __shared__ int psum[32];

    int pre = 0;
    for (int i = tid; i < ch * 1024; i += 1024) pre += d_cnt[t * NN + i];

    int i = ch * 1024 + tid;
    int v = (i < NN) ? d_cnt[t * NN + i] : 0;

    int incl = v;
#pragma unroll
    for (int o = 1; o < 32; o <<= 1) {
        int u = __shfl_up_sync(0xffffffffu, incl, o);
        if (lane >= o) incl += u;
    }
#pragma unroll
    for (int o = 16; o; o >>= 1) pre += __shfl_xor_sync(0xffffffffu, pre, o);

    if (lane == 31) wsum[w] = incl;
    if (lane == 0)  psum[w] = pre;
    __syncthreads();
    if (w == 0) {
        int s = wsum[lane];
        int is = s;
#pragma unroll
        for (int o = 1; o < 32; o <<= 1) {
            int u = __shfl_up_sync(0xffffffffu, is, o);
            if (lane >= o) is += u;
        }
        wsum[lane] = is - s;
        int p = psum[lane];
#pragma unroll
        for (int o = 16; o; o >>= 1) p += __shfl_xor_sync(0xffffffffu, p, o);
        psum[lane] = p;
    }
    __syncthreads();

    int prev = psum[0];
    int blk_incl = wsum[w] + incl;

    if (i < NN) {
        int excl = prev + blk_incl - v;
        d_off[t * (NN + 1) + i] = excl;
        d_cur[t * NN + i]       = excl;
    }
    if (ch == SCH - 1 && tid == 1023)
        d_off[t * (NN + 1) + NN] = prev + blk_incl;
}

// ---------------- GEMM: h0 += x @ W1 (tf32 mma, bulk-copy pipeline) ----------
__global__ void __launch_bounds__(256, 3)
gemm_kernel(const float* __restrict__ x) {
    extern __shared__ __align__(16) char smem[];
    __shared__ __align__(8) unsigned long long mbar_st[STg];

    const int tid  = threadIdx.x;
    const int lane = tid & 31;
    const int warp = tid >> 5;
    const int m0   = blockIdx.x * BMg;
    const int tile0 = blockIdx.y * TPC;
    const int ntile = min(TPC, NTILE_TOT - tile0);
    const int V     = min(BMg, NN - m0);           // valid rows in this m-block
    const int evens = (V + 1) / 2, odds = V / 2;
    const uint32_t bytes_norm = (uint32_t)(evens * 128 + odds * 144 + WTILE_BYTES);
    const uint32_t bytes_tail = (uint32_t)(V * 144 + WTILE_BYTES);

    const uint32_t sbase = smem_u32(smem);
    const uint32_t mb0   = smem_u32(&mbar_st[0]);

    if (tid == 0) {
#pragma unroll
        for (int s = 0; s < STg; s++) mbar_init(mb0 + 8 * s, 1);
        asm volatile("fence.proxy.async.shared::cta;" ::: "memory");
    }
    __syncthreads();

    // per-thread bulk-copy role
    const int r = tid;                              // row for tid<128
    const bool xrow = (tid < BMg) && (r < V);
    const int rodd = r & 1;
    const char* xsrc0 = (const char*)x
        + ((long)(m0 + r) * KD + (long)tile0 * BKg) * 4 - (rodd ? 8 : 0);
    const int xnb = rodd ? 144 : 128;
    const uint32_t xdst = (uint32_t)(r * XROWB);
    const char* xtail_src = (const char*)d_xtail + (long)(m0 + r) * XROWB;
    const bool wrow = (tid == 128);
    const char* wsrc0 = (const char*)d_w1t + (long)tile0 * WTILE_BYTES;

    auto issue_fill = [&](int buf, int tIdx) {
        const int gt = tile0 + tIdx;
        const uint32_t bar = mb0 + 8 * buf;
        const uint32_t sb  = sbase + (uint32_t)buf * STAGE_BYTES;
        if (tid == 0)
            mbar_expect(bar, (gt == NTILE_TOT - 1) ? bytes_tail : bytes_norm);
        if (xrow) {
            if (gt == NTILE_TOT - 1)
                bulk_g2s(sb + xdst, xtail_src, 144, bar);
            else
                bulk_g2s(sb + xdst, xsrc0 + (long)tIdx * (BKg * 4), xnb, bar);
        } else if (wrow) {
            bulk_g2s(sb + XTILE_BYTES, wsrc0 + (long)tIdx * WTILE_BYTES,
                     WTILE_BYTES, bar);
        }
    };

    issue_fill(0, 0);
    issue_fill(1, 1);

    float acc[4][4];
#pragma unroll
    for (int a = 0; a < 4; a++)
#pragma unroll
        for (int b = 0; b < 4; b++) acc[a][b] = 0.f;

    const int arow = warp * 16 + (lane >> 2);
    const int sh   = (arow & 1) ? 2 : 0;
    const int kq   = lane & 3;

    for (int it = 0; it < ntile; it++) {
        const int buf = it % STg;
        mbar_wait(mb0 + 8 * buf, (uint32_t)((it / STg) & 1));

        // refill buffer (it+2)%3 — its previous compute finished at it-1,
        // guaranteed by the __syncthreads at the end of iteration it-1.
        if (it + STg - 1 < ntile)
            issue_fill((it + STg - 1) % STg, it + STg - 1);

        const float*    xb = (const float*)(smem + buf * STAGE_BYTES);
        const uint32_t* wb = (const uint32_t*)(smem + buf * STAGE_BYTES + XTILE_BYTES);
#pragma unroll
        for (int s = 0; s < 4; s++) {
            const int k8 = s * 8;
            uint32_t a0 = __float_as_uint(xb[arow * XSTR + sh + k8 + kq]);
            uint32_t a1 = __float_as_uint(xb[(arow + 8) * XSTR + sh + k8 + kq]);
            uint32_t a2 = __float_as_uint(xb[arow * XSTR + sh + k8 + 4 + kq]);
            uint32_t a3 = __float_as_uint(xb[(arow + 8) * XSTR + sh + k8 + 4 + kq]);
            uint4 va = *(const uint4*)(wb + s * 256 + lane * 4);
            uint4 vb = *(const uint4*)(wb + s * 256 + 128 + lane * 4);
            const uint32_t* b0q = &va.x;
            const uint32_t* b1q = &vb.x;
#pragma unroll
            for (int nt = 0; nt < 4; nt++) {
                asm volatile(
                    "mma.sync.aligned.m16n8k8.row.col.f32.tf32.tf32.f32 "
                    "{%0,%1,%2,%3}, {%4,%5,%6,%7}, {%8,%9}, {%0,%1,%2,%3};\n"
                    : "+f"(acc[nt][0]), "+f"(acc[nt][1]), "+f"(acc[nt][2]), "+f"(acc[nt][3])
                    : "r"(a0), "r"(a1), "r"(a2), "r"(a3), "r"(b0q[nt]), "r"(b1q[nt]));
            }
        }
        __syncthreads();   // compute(it) done before buf is refilled at it+3
    }

    // split-K epilogue: atomic accumulate
    const int r0 = m0 + arow;
    const int r1 = r0 + 8;
    const int c0 = (lane & 3) * 2;
#pragma unroll
    for (int nt = 0; nt < 4; nt++) {
        int c = nt * 8 + c0;
        if (r0 < NN) {
            atomicAdd(&d_h0[r0 * HD + c],     acc[nt][0]);
            atomicAdd(&d_h0[r0 * HD + c + 1], acc[nt][1]);
        }
        if (r1 < NN) {
            atomicAdd(&d_h0[r1 * HD + c],     acc[nt][2]);
            atomicAdd(&d_h0[r1 * HD + c + 1], acc[nt][3]);
        }
    }
}

// ---------------- scatter edges into CSR (packed (eid<<32)|src) --------------
__global__ void scatter_kernel(const int* __restrict__ ei, const float* __restrict__ ew) {
    int idx = blockIdx.x * 256 + threadIdx.x;
    if (idx >= TT * EE) return;
    int f = i64_flag(ei);
    int t = idx / EE, e = idx - t * EE;
    int i = ld_idx(ei, t * 2 * EE + e, f);
    int j = ld_idx(ei, t * 2 * EE + EE + e, f);
    int pos = atomicAdd(&d_cur[t * NN + j], 1);
    d_se[t * EE + pos] = ((unsigned long long)(unsigned)e << 32) | (unsigned)i;
    d_wb[t * EE + pos] = ew[idx];
}

// ---------------- dedup: warp-shuffle fast path (deg <= 32) ------------------
__global__ void __launch_bounds__(256) dedup_kernel() {
    int gw   = (blockIdx.x * 256 + threadIdx.x) >> 5;
    int lane = threadIdx.x & 31;
    if (gw >= TT * NN) return;
    int t = gw / NN, j = gw - t * NN;
    int beg = d_off[t * (NN + 1) + j];
    int end = d_off[t * (NN + 1) + j + 1];
    int deg = end - beg;

    float sum = 0.f;
    int selfw = 0;
    if (deg <= 32) {
        unsigned long long pk = 0; float w = 0.f; int active = (lane < deg);
        if (active) { pk = d_se[t * EE + beg + lane]; w = d_wb[t * EE + beg + lane]; }
        int win = active;
        for (int q = 0; q < deg; q++) {
            unsigned long long oq = __shfl_sync(0xffffffffu, pk, q);
            if (active && q != lane && (unsigned)oq == (unsigned)pk && oq > pk) win = 0;
        }
        if (active) {
            if (win) {
                sum = w;
                if ((int)(unsigned)pk == j) selfw = 1;
            } else {
                d_wb[t * EE + beg + lane] = 0.f;
            }
        }
    } else {
        for (int p = beg + lane; p < end; p += 32) {
            unsigned long long pk = d_se[t * EE + p];
            bool win = true;
            for (int q = beg; q < end; q++) {
                unsigned long long oq = d_se[t * EE + q];
                if (q != p && (unsigned)oq == (unsigned)pk && oq > pk) { win = false; break; }
            }
            if (win) {
                sum += d_wb[t * EE + p];
                if ((int)(unsigned)pk == j) selfw = 1;
            } else {
                d_wb[t * EE + p] = 0.f;
            }
        }
    }
#pragma unroll
    for (int o = 16; o; o >>= 1) {
        sum   += __shfl_xor_sync(0xffffffffu, sum, o);
        selfw |= __shfl_xor_sync(0xffffffffu, selfw, o);
    }
    if (lane == 0) {
        float diag = selfw ? 0.f : 1.f;
        d_diag[t * NN + j] = diag;
        d_dinv[t * NN + j] = rsqrtf(diag + sum);
    }
}

// ---------------- SpMM1 + ReLU + (h @ W2), p-loop unrolled x4 ----------------
__global__ void __launch_bounds__(256) spmm1_kernel(const float* __restrict__ b1,
                                                    const float* __restrict__ W2) {
    __shared__ float hs[8][HD];
    int gw   = (blockIdx.x * 256 + threadIdx.x) >> 5;
    int lane = threadIdx.x & 31;
    int wib  = (threadIdx.x >> 5);
    if (gw >= TT * NN) return;
    int t = gw / NN, j = gw - t * NN;
    const int tE = t * EE, tN = t * NN;
    int beg = d_off[t * (NN + 1) + j];
    int end = d_off[t * (NN + 1) + j + 1];

    float dj  = d_dinv[tN + j];
    float acc = d_diag[tN + j] * dj * d_h0[j * HD + lane];
    int p = beg;
    for (; p + 4 <= end; p += 4) {
        int s0 = (int)(unsigned)d_se[tE + p];
        int s1 = (int)(unsigned)d_se[tE + p + 1];
        int s2 = (int)(unsigned)d_se[tE + p + 2];
        int s3 = (int)(unsigned)d_se[tE + p + 3];
        float c0 = d_wb[tE + p]     * d_dinv[tN + s0];
        float c1 = d_wb[tE + p + 1] * d_dinv[tN + s1];
        float c2 = d_wb[tE + p + 2] * d_dinv[tN + s2];
        float c3 = d_wb[tE + p + 3] * d_dinv[tN + s3];
        float v0 = d_h0[s0 * HD + lane], v1 = d_h0[s1 * HD + lane];
        float v2 = d_h0[s2 * HD + lane], v3 = d_h0[s3 * HD + lane];
        acc = fmaf(c0, v0, acc); acc = fmaf(c1, v1, acc);
        acc = fmaf(c2, v2, acc); acc = fmaf(c3, v3, acc);
    }
    for (; p < end; p++) {
        int s = (int)(unsigned)d_se[tE + p];
        acc = fmaf(d_wb[tE + p] * d_dinv[tN + s], d_h0[s * HD + lane], acc);
    }
    float h = fmaxf(fmaf(acc, dj, b1[lane]), 0.f);
    hs[wib][lane] = h;
    __syncwarp();
    if (lane < ZD) {
        float s = 0.f;
#pragma unroll
        for (int c = 0; c < HD; c++) s = fmaf(hs[wib][c], W2[c * ZD + lane], s);
        d_g[(size_t)gw * ZD + lane] = s;
    }
}

// ---------------- SpMM2 + tanh (2 nodes/warp), p-loop unrolled x4 ------------
__global__ void __launch_bounds__(256) spmm2_kernel(const float* __restrict__ b2,
                                                    float* __restrict__ out) {
    int gwarp = (blockIdx.x * 256 + threadIdx.x) >> 5;
    int lane  = threadIdx.x & 31;
    int half  = lane >> 4, k = lane & 15;
    int node  = gwarp * 2 + half;
    if (node >= TT * NN) return;
    int t = node / NN, j = node - t * NN;
    const int tE = t * EE, tN = t * NN;
    int beg = d_off[t * (NN + 1) + j];
    int end = d_off[t * (NN + 1) + j + 1];

    float dj  = d_dinv[tN + j];
    float acc = d_diag[tN + j] * dj * d_g[(size_t)node * ZD + k];
    int p = beg;
    for (; p + 4 <= end; p += 4) {
        int s0 = (int)(unsigned)d_se[tE + p];
        int s1 = (int)(unsigned)d_se[tE + p + 1];
        int s2 = (int)(unsigned)d_se[tE + p + 2];
        int s3 = (int)(unsigned)d_se[tE + p + 3];
        float c0 = d_wb[tE + p]     * d_dinv[tN + s0];
        float c1 = d_wb[tE + p + 1] * d_dinv[tN + s1];
        float c2 = d_wb[tE + p + 2] * d_dinv[tN + s2];
        float c3 = d_wb[tE + p + 3] * d_dinv[tN + s3];
        float v0 = d_g[(size_t)(tN + s0) * ZD + k], v1 = d_g[(size_t)(tN + s1) * ZD + k];
        float v2 = d_g[(size_t)(tN + s2) * ZD + k], v3 = d_g[(size_t)(tN + s3) * ZD + k];
        acc = fmaf(c0, v0, acc); acc = fmaf(c1, v1, acc);
        acc = fmaf(c2, v2, acc); acc = fmaf(c3, v3, acc);
    }
    for (; p < end; p++) {
        int s = (int)(unsigned)d_se[tE + p];
        acc = fmaf(d_wb[tE + p] * d_dinv[tN + s], d_g[(size_t)(tN + s) * ZD + k], acc);
    }
    out[(size_t)node * ZD + k] = tanhf(fmaf(acc, dj, b2[k]));
}

// ---------------- launch (8 launches, R10 structure) --------------------------
extern "C" void kernel_launch(void* const* d_in, const int* in_sizes, int n_in,
                              void* d_out, int out_size) {
    const float* x  = (const float*)d_in[0];
    const int*   ei = (const int*)d_in[1];
    const float* ew = (const float*)d_in[2];
    const float* W1 = (const float*)d_in[3];
    const float* b1 = (const float*)d_in[4];
    const float* W2 = (const float*)d_in[5];
    const float* b2 = (const float*)d_in[6];
    float* out = (float*)d_out;

    cudaFuncSetAttribute(gemm_kernel, cudaFuncAttributeMaxDynamicSharedMemorySize, GEMM_SMEM);

    prep_kernel<<<(PREP_TOT + 255) / 256, 256>>>(W1, x);              // 1
    hist_kernel<<<(TT * EE + 255) / 256, 256>>>(ei);                  // 2
    scan_kernel<<<dim3(SCH, TT), 1024>>>();                           // 3
    gemm_kernel<<<dim3((NN + BMg - 1) / BMg, KSPLIT), 256, GEMM_SMEM>>>(x);  // 4
    scatter_kernel<<<(TT * EE + 255) / 256, 256>>>(ei, ew);           // 5
    dedup_kernel<<<(TT * NN * 32 + 255) / 256, 256>>>();              // 6
    spmm1_kernel<<<(TT * NN * 32 + 255) / 256, 256>>>(b1, W2);        // 7
    spmm2_kernel<<<(TT * NN * 16 + 255) / 256, 256>>>(b2, out);       // 8
}

// round 15
// speedup vs baseline: 1.0304x; 1.0304x over previous
#include <cuda_runtime.h>
#include <cstdint>
#include <math.h>

#define NN 8746
#define KD 8746
#define HD 32
#define ZD 16
#define TT 6
#define EE 100000

// GEMM tiling (R10 exact): BM=128, BK=32, split-K x6, 3-stage cp.async pipe
#define BMg 128
#define BKg 32
#define STg 3
#define KSPLIT 6
#define TPC 46
#define NTILE_TOT 274
#define XSTR 36
#define XTILE_BYTES (BMg * XSTR * 4)
#define WTILE_WORDS (BKg * HD)
#define WTILE_BYTES (WTILE_WORDS * 4)
#define GEMM_SMEM (STg * (XTILE_BYTES + WTILE_BYTES))   // 67584

#define SCH 9

// ---------------- scratch (device globals; no allocations allowed) ----------
__device__ float    d_h0[NN * HD];
__device__ uint32_t d_w1t[NTILE_TOT * WTILE_WORDS];
__device__ int      d_cnt[TT * NN];
__device__ int      d_off[TT * (NN + 1)];
__device__ int      d_cur[TT * NN];
__device__ unsigned long long d_se[TT * EE];   // packed (eid<<32)|src
__device__ float    d_wb[TT * EE];
__device__ float    d_diag[TT * NN];
__device__ float    d_dinv[TT * NN];
__device__ float    d_g[TT * NN * ZD];         // stores dinv-prescaled g'

// ---------------- helpers ---------------------------------------------------
__device__ __forceinline__ void cp16(uint32_t dst, const void* src, int nb) {
    asm volatile("cp.async.cg.shared.global [%0], [%1], 16, %2;\n"
                 :: "r"(dst), "l"(src), "r"(nb) : "memory");
}
__device__ __forceinline__ uint32_t f2tf(float f) {
    uint32_t r;
    asm("cvt.rna.tf32.f32 %0, %1;" : "=r"(r) : "f"(f));
    return r;
}
__device__ __forceinline__ int ld_idx(const int* ei, int pos, int f) {
    return f ? ei[2 * pos] : ei[pos];
}
__device__ __forceinline__ int i64_flag(const int* ei) {
    return ((ei[1] | ei[3] | ei[5] | ei[7] | ei[9]) == 0) ? 1 : 0;
}

// ---------------- fused prep: zero h0/cnt + W1->tf32 fragment layout ---------
#define PREP_H0 (NN * HD)
#define PREP_CNT (TT * NN)
#define PREP_W1 (NTILE_TOT * WTILE_WORDS)
#define PREP_TOT (PREP_H0 + PREP_CNT + PREP_W1)
__global__ void prep_kernel(const float* __restrict__ W1) {
    int idx = blockIdx.x * 256 + threadIdx.x;
    if (idx < PREP_H0) {
        d_h0[idx] = 0.f;
    } else if (idx < PREP_H0 + PREP_CNT) {
        d_cnt[idx - PREP_H0] = 0;
    } else if (idx < PREP_TOT) {
        int w = idx - PREP_H0 - PREP_CNT;
        int kt = w >> 10, r = w & 1023;
        int s = r >> 8, r2 = r & 255;
        int half = (r2 >> 7) & 1;
        int l = (r2 >> 2) & 31;
        int j = r2 & 3;
        int k = kt * 32 + s * 8 + (l & 3) + half * 4;
        int n = (l >> 2) + j * 8;
        d_w1t[w] = (k < KD) ? f2tf(W1[k * HD + n]) : 0u;
    }
}

// ---------------- edge histogram --------------------------------------------
__global__ void hist_kernel(const int* __restrict__ ei) {
    int idx = blockIdx.x * 256 + threadIdx.x;
    if (idx >= TT * EE) return;
    int f = i64_flag(ei);
    int t = idx / EE, e = idx - t * EE;
    int j = ld_idx(ei, t * 2 * EE + EE + e, f);
    atomicAdd(&d_cnt[t * NN + j], 1);
}

// ---------------- scan: redundant prefix -------------------------------------
__global__ void __launch_bounds__(1024) scan_kernel() {
    const int t   = blockIdx.y;
    const int ch  = blockIdx.x;
    const int tid = threadIdx.x;
    const int lane = tid & 31, w = tid >> 5;
    __shared__ int wsum[32];
    __shared__ int psum[32];

    int pre = 0;
    for (int i = tid; i < ch * 1024; i += 1024) pre += d_cnt[t * NN + i];

    int i = ch * 1024 + tid;
    int v = (i < NN) ? d_cnt[t * NN + i] : 0;

    int incl = v;
#pragma unroll
    for (int o = 1; o < 32; o <<= 1) {
        int u = __shfl_up_sync(0xffffffffu, incl, o);
        if (lane >= o) incl += u;
    }
#pragma unroll
    for (int o = 16; o; o >>= 1) pre += __shfl_xor_sync(0xffffffffu, pre, o);

    if (lane == 31) wsum[w] = incl;
    if (lane == 0)  psum[w] = pre;
    __syncthreads();
    if (w == 0) {
        int s = wsum[lane];
        int is = s;
#pragma unroll
        for (int o = 1; o < 32; o <<= 1) {
            int u = __shfl_up_sync(0xffffffffu, is, o);
            if (lane >= o) is += u;
        }
        wsum[lane] = is - s;
        int p = psum[lane];
#pragma unroll
        for (int o = 16; o; o >>= 1) p += __shfl_xor_sync(0xffffffffu, p, o);
        psum[lane] = p;
    }
    __syncthreads();

    int prev = psum[0];
    int blk_incl = wsum[w] + incl;

    if (i < NN) {
        int excl = prev + blk_incl - v;
        d_off[t * (NN + 1) + i] = excl;
        d_cur[t * NN + i]       = excl;
    }
    if (ch == SCH - 1 && tid == 1023)
        d_off[t * (NN + 1) + NN] = prev + blk_incl;
}

// ---------------- GEMM: h0 += x @ W1 (R10 exact: tf32 mma, cp.async) ---------
__global__ void __launch_bounds__(256, 3)
gemm_kernel(const float* __restrict__ x) {
    extern __shared__ __align__(16) char smem[];
    float*    xs = (float*)smem;
    uint32_t* ws = (uint32_t*)(smem + STg * XTILE_BYTES);

    const int tid  = threadIdx.x;
    const int lane = tid & 31;
    const int warp = tid >> 5;
    const int m0   = blockIdx.x * BMg;
    const int tile0 = blockIdx.y * TPC;
    const int ntile = min(TPC, NTILE_TOT - tile0);
    const bool clampblk = (m0 + BMg > NN);
    const char* xbase = (const char*)x;
    const uint32_t XENDB = (uint32_t)((long)NN * KD * 4);

    const uint32_t xs_u = (uint32_t)__cvta_generic_to_shared(xs);
    const uint32_t ws_u = (uint32_t)__cvta_generic_to_shared(ws);

    uint32_t xoff[5], xdst[5];
    int xok[5];
#pragma unroll
    for (int i = 0; i < 5; i++) {
        int q = i * 32 + lane;
        xok[i] = 0; xoff[i] = 0;
        if (q < 136) {
            int pair = q / 17, k = q - pair * 17;
            int odd  = (k >= 8) ? 1 : 0;
            int row  = warp * 16 + pair * 2 + odd;
            int cc   = odd ? (k - 8) : k;
            if (!(clampblk && row >= NN - m0)) {
                xoff[i] = (uint32_t)(((long)(m0 + row) * KD + tile0 * BKg + cc * 4
                                      - (odd ? 2 : 0)) * 4);
                xdst[i] = (uint32_t)(row * XSTR + cc * 4) * 4;
                xok[i]  = 1;
            }
        }
    }
    const char* wsrc = (const char*)d_w1t + (long)tile0 * WTILE_BYTES + tid * 16;

    auto load_tiles = [&](int buf) {
        const uint32_t xb = xs_u + (uint32_t)buf * XTILE_BYTES;
#pragma unroll
        for (int i = 0; i < 5; i++) {
            if (xok[i]) {
                uint32_t o = xoff[i];
                int nb = 16;
                if (clampblk) {
                    if (o >= XENDB) { nb = 0; o = 0; }
                    else if (XENDB - o < 16) nb = (int)(XENDB - o);
                }
                cp16(xb + xdst[i], xbase + o, nb);
                xoff[i] += BKg * 4;
            }
        }
        cp16(ws_u + (uint32_t)buf * WTILE_BYTES + (uint32_t)tid * 16, wsrc, 16);
        wsrc += WTILE_BYTES;
    };

#pragma unroll
    for (int s = 0; s < STg - 1; s++) {
        load_tiles(s);
        asm volatile("cp.async.commit_group;\n" ::: "memory");
    }

    float acc[4][4];
#pragma unroll
    for (int a = 0; a < 4; a++)
#pragma unroll
        for (int b = 0; b < 4; b++) acc[a][b] = 0.f;

    const int arow = warp * 16 + (lane >> 2);
    const int sh   = (arow & 1) ? 2 : 0;
    const int kq   = lane & 3;

    int cbuf = 0, lbuf = STg - 1;
    for (int it = 0; it < ntile; it++) {
        asm volatile("cp.async.wait_group %0;\n" :: "n"(STg - 2) : "memory");
        __syncthreads();

        if (it + STg - 1 < ntile)
            load_tiles(lbuf);
        asm volatile("cp.async.commit_group;\n" ::: "memory");
        lbuf = (lbuf == STg - 1) ? 0 : lbuf + 1;

        const float*    xb = xs + cbuf * (BMg * XSTR);
        const uint32_t* wb = ws + cbuf * WTILE_WORDS;
        cbuf = (cbuf == STg - 1) ? 0 : cbuf + 1;
#pragma unroll
        for (int s = 0; s < 4; s++) {
            const int k8 = s * 8;
            uint32_t a0 = __float_as_uint(xb[arow * XSTR + sh + k8 + kq]);
            uint32_t a1 = __float_as_uint(xb[(arow + 8) * XSTR + sh + k8 + kq]);
            uint32_t a2 = __float_as_uint(xb[arow * XSTR + sh + k8 + 4 + kq]);
            uint32_t a3 = __float_as_uint(xb[(arow + 8) * XSTR + sh + k8 + 4 + kq]);
            uint4 va = *(const uint4*)(wb + s * 256 + lane * 4);
            uint4 vb = *(const uint4*)(wb + s * 256 + 128 + lane * 4);
            const uint32_t* b0q = &va.x;
            const uint32_t* b1q = &vb.x;
#pragma unroll
            for (int nt = 0; nt < 4; nt++) {
                asm volatile(
                    "mma.sync.aligned.m16n8k8.row.col.f32.tf32.tf32.f32 "
                    "{%0,%1,%2,%3}, {%4,%5,%6,%7}, {%8,%9}, {%0,%1,%2,%3};\n"
                    : "+f"(acc[nt][0]), "+f"(acc[nt][1]), "+f"(acc[nt][2]), "+f"(acc[nt][3])
                    : "r"(a0), "r"(a1), "r"(a2), "r"(a3), "r"(b0q[nt]), "r"(b1q[nt]));
            }
        }
    }

    const int r0 = m0 + arow;
    const int r1 = r0 + 8;
    const int c0 = (lane & 3) * 2;
#pragma unroll
    for (int nt = 0; nt < 4; nt++) {
        int c = nt * 8 + c0;
        if (r0 < NN) {
            atomicAdd(&d_h0[r0 * HD + c],     acc[nt][0]);
            atomicAdd(&d_h0[r0 * HD + c + 1], acc[nt][1]);
        }
        if (r1 < NN) {
            atomicAdd(&d_h0[r1 * HD + c],     acc[nt][2]);
            atomicAdd(&d_h0[r1 * HD + c + 1], acc[nt][3]);
        }
    }
}

// ---------------- scatter edges into CSR (packed (eid<<32)|src) --------------
__global__ void scatter_kernel(const int* __restrict__ ei, const float* __restrict__ ew) {
    int idx = blockIdx.x * 256 + threadIdx.x;
    if (idx >= TT * EE) return;
    int f = i64_flag(ei);
    int t = idx / EE, e = idx - t * EE;
    int i = ld_idx(ei, t * 2 * EE + e, f);
    int j = ld_idx(ei, t * 2 * EE + EE + e, f);
    int pos = atomicAdd(&d_cur[t * NN + j], 1);
    d_se[t * EE + pos] = ((unsigned long long)(unsigned)e << 32) | (unsigned)i;
    d_wb[t * EE + pos] = ew[idx];
}

// ---------------- dedup: warp-shuffle fast path (deg <= 32) ------------------
__global__ void __launch_bounds__(256) dedup_kernel() {
    int gw   = (blockIdx.x * 256 + threadIdx.x) >> 5;
    int lane = threadIdx.x & 31;
    if (gw >= TT * NN) return;
    int t = gw / NN, j = gw - t * NN;
    int beg = d_off[t * (NN + 1) + j];
    int end = d_off[t * (NN + 1) + j + 1];
    int deg = end - beg;

    float sum = 0.f;
    int selfw = 0;
    if (deg <= 32) {
        unsigned long long pk = 0; float w = 0.f; int active = (lane < deg);
        if (active) { pk = d_se[t * EE + beg + lane]; w = d_wb[t * EE + beg + lane]; }
        int win = active;
        for (int q = 0; q < deg; q++) {
            unsigned long long oq = __shfl_sync(0xffffffffu, pk, q);
            if (active && q != lane && (unsigned)oq == (unsigned)pk && oq > pk) win = 0;
        }
        if (active) {
            if (win) {
                sum = w;
                if ((int)(unsigned)pk == j) selfw = 1;
            } else {
                d_wb[t * EE + beg + lane] = 0.f;
            }
        }
    } else {
        for (int p = beg + lane; p < end; p += 32) {
            unsigned long long pk = d_se[t * EE + p];
            bool win = true;
            for (int q = beg; q < end; q++) {
                unsigned long long oq = d_se[t * EE + q];
                if (q != p && (unsigned)oq == (unsigned)pk && oq > pk) { win = false; break; }
            }
            if (win) {
                sum += d_wb[t * EE + p];
                if ((int)(unsigned)pk == j) selfw = 1;
            } else {
                d_wb[t * EE + p] = 0.f;
            }
        }
    }
#pragma unroll
    for (int o = 16; o; o >>= 1) {
        sum   += __shfl_xor_sync(0xffffffffu, sum, o);
        selfw |= __shfl_xor_sync(0xffffffffu, selfw, o);
    }
    if (lane == 0) {
        float diag = selfw ? 0.f : 1.f;
        d_diag[t * NN + j] = diag;
        d_dinv[t * NN + j] = rsqrtf(diag + sum);
    }
}

// ---------------- SpMM1 + ReLU + (h @ W2); stores g' = dinv_j * g ------------
__global__ void __launch_bounds__(256) spmm1_kernel(const float* __restrict__ b1,
                                                    const float* __restrict__ W2) {
    __shared__ float hs[8][HD];
    int gw   = (blockIdx.x * 256 + threadIdx.x) >> 5;
    int lane = threadIdx.x & 31;
    int wib  = (threadIdx.x >> 5);
    if (gw >= TT * NN) return;
    int t = gw / NN, j = gw - t * NN;
    const int tE = t * EE, tN = t * NN;
    int beg = d_off[t * (NN + 1) + j];
    int end = d_off[t * (NN + 1) + j + 1];

    float dj  = d_dinv[tN + j];
    float acc = d_diag[tN + j] * dj * d_h0[j * HD + lane];
    int p = beg;
    for (; p + 4 <= end; p += 4) {
        int s0 = (int)(unsigned)d_se[tE + p];
        int s1 = (int)(unsigned)d_se[tE + p + 1];
        int s2 = (int)(unsigned)d_se[tE + p + 2];
        int s3 = (int)(unsigned)d_se[tE + p + 3];
        float c0 = d_wb[tE + p]     * d_dinv[tN + s0];
        float c1 = d_wb[tE + p + 1] * d_dinv[tN + s1];
        float c2 = d_wb[tE + p + 2] * d_dinv[tN + s2];
        float c3 = d_wb[tE + p + 3] * d_dinv[tN + s3];
        float v0 = d_h0[s0 * HD + lane], v1 = d_h0[s1 * HD + lane];
        float v2 = d_h0[s2 * HD + lane], v3 = d_h0[s3 * HD + lane];
        acc = fmaf(c0, v0, acc); acc = fmaf(c1, v1, acc);
        acc = fmaf(c2, v2, acc); acc = fmaf(c3, v3, acc);
    }
    for (; p < end; p++) {
        int s = (int)(unsigned)d_se[tE + p];
        acc = fmaf(d_wb[tE + p] * d_dinv[tN + s], d_h0[s * HD + lane], acc);
    }
    float h = fmaxf(fmaf(acc, dj, b1[lane]), 0.f);
    hs[wib][lane] = h;
    __syncwarp();
    if (lane < ZD) {
        float s = 0.f;
#pragma unroll
        for (int c = 0; c < HD; c++) s = fmaf(hs[wib][c], W2[c * ZD + lane], s);
        d_g[(size_t)gw * ZD + lane] = s * dj;    // pre-scale by dinv_j
    }
}

// ---------------- SpMM2 + tanh (2 nodes/warp), g pre-scaled ------------------
__global__ void __launch_bounds__(256) spmm2_kernel(const float* __restrict__ b2,
                                                    float* __restrict__ out) {
    int gwarp = (blockIdx.x * 256 + threadIdx.x) >> 5;
    int lane  = threadIdx.x & 31;
    int half  = lane >> 4, k = lane & 15;
    int node  = gwarp * 2 + half;
    if (node >= TT * NN) return;
    int t = node / NN, j = node - t * NN;
    const int tE = t * EE, tN = t * NN;
    int beg = d_off[t * (NN + 1) + j];
    int end = d_off[t * (NN + 1) + j + 1];

    float dj  = d_dinv[tN + j];
    // g' = dinv*g already: diag*dj*g[node] == diag*g'[node]; w*dinv_s*g[s] == w*g'[s]
    float acc = d_diag[tN + j] * d_g[(size_t)node * ZD + k];
    int p = beg;
    for (; p + 4 <= end; p += 4) {
        int s0 = (int)(unsigned)d_se[tE + p];
        int s1 = (int)(unsigned)d_se[tE + p + 1];
        int s2 = (int)(unsigned)d_se[tE + p + 2];
        int s3 = (int)(unsigned)d_se[tE + p + 3];
        float c0 = d_wb[tE + p],     c1 = d_wb[tE + p + 1];
        float c2 = d_wb[tE + p + 2], c3 = d_wb[tE + p + 3];
        float v0 = d_g[(size_t)(tN + s0) * ZD + k], v1 = d_g[(size_t)(tN + s1) * ZD + k];
        float v2 = d_g[(size_t)(tN + s2) * ZD + k], v3 = d_g[(size_t)(tN + s3) * ZD + k];
        acc = fmaf(c0, v0, acc); acc = fmaf(c1, v1, acc);
        acc = fmaf(c2, v2, acc); acc = fmaf(c3, v3, acc);
    }
    for (; p < end; p++) {
        int s = (int)(unsigned)d_se[tE + p];
        acc = fmaf(d_wb[tE + p], d_g[(size_t)(tN + s) * ZD + k], acc);
    }
    out[(size_t)node * ZD + k] = tanhf(fmaf(acc, dj, b2[k]));
}

// ---------------- launch (8 launches; dedup = profiled slot 6) ---------------
extern "C" void kernel_launch(void* const* d_in, const int* in_sizes, int n_in,
                              void* d_out, int out_size) {
    const float* x  = (const float*)d_in[0];
    const int*   ei = (const int*)d_in[1];
    const float* ew = (const float*)d_in[2];
    const float* W1 = (const float*)d_in[3];
    const float* b1 = (const float*)d_in[4];
    const float* W2 = (const float*)d_in[5];
    const float* b2 = (const float*)d_in[6];
    float* out = (float*)d_out;

    cudaFuncSetAttribute(gemm_kernel, cudaFuncAttributeMaxDynamicSharedMemorySize, GEMM_SMEM);

    prep_kernel<<<(PREP_TOT + 255) / 256, 256>>>(W1);                 // 1
    hist_kernel<<<(TT * EE + 255) / 256, 256>>>(ei);                  // 2
    scan_kernel<<<dim3(SCH, TT), 1024>>>();                           // 3
    gemm_kernel<<<dim3((NN + BMg - 1) / BMg, KSPLIT), 256, GEMM_SMEM>>>(x);  // 4
    scatter_kernel<<<(TT * EE + 255) / 256, 256>>>(ei, ew);           // 5
    dedup_kernel<<<(TT * NN * 32 + 255) / 256, 256>>>();              // 6 (profiled)
    spmm1_kernel<<<(TT * NN * 32 + 255) / 256, 256>>>(b1, W2);        // 7
    spmm2_kernel<<<(TT * NN * 16 + 255) / 256, 256>>>(b2, out);       // 8
}

// round 16
// speedup vs baseline: 1.0970x; 1.0646x over previous
#include <cuda_runtime.h>
#include <cstdint>
#include <math.h>

#define NN 8746
#define KD 8746
#define HD 32
#define ZD 16
#define TT 6
#define EE 100000

// GEMM: BM=128, BK=128, split-K x2 (grid 138 = 1 block/SM), 2-stage TMA bulk
#define BMg 128
#define BKg 128
#define STg 2
#define KSPLIT 2
#define TPC 35
#define NTILE_TOT 69                     // ceil(8746/128)
#define KTAIL0 (68 * BKg)                // 8704; valid tail cols = 42
#define XSTR2 132                        // smem row stride in floats (528B)
#define XROWB2 (XSTR2 * 4)               // 528
#define XTILE_BYTES (BMg * XROWB2)       // 67584
#define WSUB_WORDS 1024                  // fragment-ordered 32-k sub-block
#define WTILE_BYTES (4 * WSUB_WORDS * 4) // 16384
#define STAGE_BYTES (XTILE_BYTES + WTILE_BYTES)  // 83968
#define GEMM_SMEM (STg * STAGE_BYTES)    // 167936

#define SCH 9

// ---------------- scratch (device globals; no allocations allowed) ----------
__device__ float    d_h0[NN * HD];
__device__ uint32_t d_w1t[(NTILE_TOT * 4) * WSUB_WORDS];  // 276 kt32 blocks (padded)
__device__ float    d_xtail[NN * XSTR2];       // tail k-tile, pre-shifted + padded
__device__ int      d_cnt[TT * NN];
__device__ int      d_off[TT * (NN + 1)];
__device__ int      d_cur[TT * NN];
__device__ unsigned long long d_se[TT * EE];   // packed (eid<<32)|src
__device__ float    d_wb[TT * EE];
__device__ float    d_diag[TT * NN];
__device__ float    d_dinv[TT * NN];
__device__ float    d_g[TT * NN * ZD];         // stores dinv-prescaled g'

// ---------------- helpers ---------------------------------------------------
__device__ __forceinline__ uint32_t f2tf(float f) {
    uint32_t r;
    asm("cvt.rna.tf32.f32 %0, %1;" : "=r"(r) : "f"(f));
    return r;
}
__device__ __forceinline__ int ld_idx(const int* ei, int pos, int f) {
    return f ? ei[2 * pos] : ei[pos];
}
__device__ __forceinline__ int i64_flag(const int* ei) {
    return ((ei[1] | ei[3] | ei[5] | ei[7] | ei[9]) == 0) ? 1 : 0;
}
__device__ __forceinline__ uint32_t smem_u32(const void* p) {
    return (uint32_t)__cvta_generic_to_shared(p);
}
__device__ __forceinline__ void bulk_g2s(uint32_t dst, const void* src, int nb,
                                         uint32_t mbar) {
    asm volatile(
        "cp.async.bulk.shared::cta.global.mbarrier::complete_tx::bytes "
        "[%0], [%1], %2, [%3];\n"
        :: "r"(dst), "l"(src), "r"(nb), "r"(mbar) : "memory");
}
__device__ __forceinline__ void mbar_init(uint32_t mbar, uint32_t cnt) {
    asm volatile("mbarrier.init.shared.b64 [%0], %1;" :: "r"(mbar), "r"(cnt) : "memory");
}
__device__ __forceinline__ void mbar_expect(uint32_t mbar, uint32_t bytes) {
    asm volatile("mbarrier.arrive.expect_tx.shared.b64 _, [%0], %1;"
                 :: "r"(mbar), "r"(bytes) : "memory");
}
__device__ __forceinline__ void mbar_wait(uint32_t mbar, uint32_t parity) {
    uint32_t done;
    asm volatile(
        "{\n\t.reg .pred p;\n\t"
        "mbarrier.try_wait.parity.acquire.cta.shared::cta.b64 p, [%1], %2;\n\t"
        "selp.b32 %0, 1, 0, p;\n\t}"
        : "=r"(done) : "r"(mbar), "r"(parity) : "memory");
    if (!done) {
        asm volatile(
            "{\n\t.reg .pred P1;\n\t"
            "WL_%=:\n\t"
            "mbarrier.try_wait.parity.acquire.cta.shared::cta.b64 P1, [%0], %1, 0x989680;\n\t"
            "@P1 bra.uni WD_%=;\n\t"
            "bra.uni WL_%=;\n\t"
            "WD_%=:\n\t}"
            :: "r"(mbar), "r"(parity) : "memory");
    }
}

// ---------------- fused prep: h0/cnt zero + W1->tf32 + xtail staging ---------
#define PREP_H0 (NN * HD)
#define PREP_CNT (TT * NN)
#define PREP_W1 ((NTILE_TOT * 4) * WSUB_WORDS)
#define PREP_XT (NN * XSTR2)
#define PREP_TOT (PREP_H0 + PREP_CNT + PREP_W1 + PREP_XT)
__global__ void prep_kernel(const float* __restrict__ W1, const float* __restrict__ x) {
    int idx = blockIdx.x * 256 + threadIdx.x;
    if (idx < PREP_H0) {
        d_h0[idx] = 0.f;
    } else if (idx < PREP_H0 + PREP_CNT) {
        d_cnt[idx - PREP_H0] = 0;
    } else if (idx < PREP_H0 + PREP_CNT + PREP_W1) {
        int w = idx - PREP_H0 - PREP_CNT;
        int kt = w >> 10, r = w & 1023;
        int s = r >> 8, r2 = r & 255;
        int half = (r2 >> 7) & 1;
        int l = (r2 >> 2) & 31;
        int j = r2 & 3;
        int k = kt * 32 + s * 8 + (l & 3) + half * 4;
        int n = (l >> 2) + j * 8;
        d_w1t[w] = (k < KD) ? f2tf(W1[k * HD + n]) : 0u;
    } else if (idx < PREP_TOT) {
        int w = idx - PREP_H0 - PREP_CNT - PREP_W1;
        int r = w / XSTR2, c = w - r * XSTR2;
        int sh = (r & 1) * 2;
        int kc = c - sh;
        float v = (kc >= 0 && kc < KD - KTAIL0) ? x[(size_t)r * KD + KTAIL0 + kc] : 0.f;
        d_xtail[w] = v;
    }
}

// ---------------- edge histogram --------------------------------------------
__global__ void hist_kernel(const int* __restrict__ ei) {
    int idx = blockIdx.x * 256 + threadIdx.x;
    if (idx >= TT * EE) return;
    int f = i64_flag(ei);
    int t = idx / EE, e = idx - t * EE;
    int j = ld_idx(ei, t * 2 * EE + EE + e, f);
    atomicAdd(&d_cnt[t * NN + j], 1);
}

// ---------------- scan: redundant prefix -------------------------------------
__global__ void __launch_bounds__(1024) scan_kernel() {
    const int t   = blockIdx.y;
    const int ch  = blockIdx.x;
    const int tid = threadIdx.x;
    const int lane = tid & 31, w = tid >> 5;
    __shared__ int wsum[32];
    __shared__ int psum[32];

    int pre = 0;
    for (int i = tid; i < ch * 1024; i += 1024) pre += d_cnt[t * NN + i];

    int i = ch * 1024 + tid;
    int v = (i < NN) ? d_cnt[t * NN + i] : 0;

    int incl = v;
#pragma unroll
    for (int o = 1; o < 32; o <<= 1) {
        int u = __shfl_up_sync(0xffffffffu, incl, o);
        if (lane >= o) incl += u;
    }
#pragma unroll
    for (int o = 16; o; o >>= 1) pre += __shfl_xor_sync(0xffffffffu, pre, o);

    if (lane == 31) wsum[w] = incl;
    if (lane == 0)  psum[w] = pre;
    __syncthreads();
    if (w == 0) {
        int s = wsum[lane];
        int is = s;
#pragma unroll
        for (int o = 1; o < 32; o <<= 1) {
            int u = __shfl_up_sync(0xffffffffu, is, o);
            if (lane >= o) is += u;
        }
        wsum[lane] = is - s;
        int p = psum[lane];
#pragma unroll
        for (int o = 16; o; o >>= 1) p += __shfl_xor_sync(0xffffffffu, p, o);
        psum[lane] = p;
    }
    __syncthreads();

    int prev = psum[0];
    int blk_incl = wsum[w] + incl;

    if (i < NN) {
        int excl = prev + blk_incl - v;
        d_off[t * (NN + 1) + i] = excl;
        d_cur[t * NN + i]       = excl;
    }
    if (ch == SCH - 1 && tid == 1023)
        d_off[t * (NN + 1) + NN] = prev + blk_incl;
}

// ---------------- GEMM: h0 += x @ W1 (tf32 mma, BK=128 TMA bulk) -------------
__global__ void __launch_bounds__(256, 1)
gemm_kernel(const float* __restrict__ x) {
    extern __shared__ __align__(16) char smem[];
    __shared__ __align__(8) unsigned long long mbar_st[STg];

    const int tid  = threadIdx.x;
    const int lane = tid & 31;
    const int warp = tid >> 5;
    const int m0   = blockIdx.x * BMg;
    const int tile0 = blockIdx.y * TPC;
    const int ntile = min(TPC, NTILE_TOT - tile0);
    const int V     = min(BMg, NN - m0);          // valid rows (last block: 42)
    const int evens = (V + 1) / 2, odds = V / 2;
    const uint32_t bytes_norm = (uint32_t)(evens * 512 + odds * 528 + WTILE_BYTES);
    const uint32_t bytes_tail = (uint32_t)(V * 528 + WTILE_BYTES);

    const uint32_t sbase = smem_u32(smem);
    const uint32_t mb0   = smem_u32(&mbar_st[0]);

    if (tid == 0) {
#pragma unroll
        for (int s = 0; s < STg; s++) mbar_init(mb0 + 8 * s, 1);
        asm volatile("fence.proxy.async.shared::cta;" ::: "memory");
    }
    __syncthreads();

    // per-thread bulk-copy role: threads 0..127 own one row, thread 128 owns W
    const int r = tid;
    const bool xrow = (tid < BMg) && (r < V);
    const int rodd = r & 1;
    // odd rows: window shifted -8B (16B-aligned since row_bytes=34984 = 8 mod 16),
    // size 528 (33x16); even rows: aligned, 512.
    const char* xsrc0 = (const char*)x
        + ((long)(m0 + r) * KD + (long)tile0 * BKg) * 4 - (rodd ? 8 : 0);
    const int xnb = rodd ? 528 : 512;
    const uint32_t xdst = (uint32_t)(r * XROWB2);
    const char* xtail_src = (const char*)d_xtail + (long)(m0 + r) * XROWB2;
    const bool wrow = (tid == 128);
    const char* wsrc_base = (const char*)d_w1t;

    auto issue_fill = [&](int buf, int tIdx) {
        const int gt = tile0 + tIdx;
        const uint32_t bar = mb0 + 8 * buf;
        const uint32_t sb  = sbase + (uint32_t)buf * STAGE_BYTES;
        if (tid == 0)
            mbar_expect(bar, (gt == NTILE_TOT - 1) ? bytes_tail : bytes_norm);
        if (xrow) {
            if (gt == NTILE_TOT - 1)
                bulk_g2s(sb + xdst, xtail_src, 528, bar);
            else
                bulk_g2s(sb + xdst, xsrc0 + (long)tIdx * (BKg * 4), xnb, bar);
        } else if (wrow) {
            bulk_g2s(sb + XTILE_BYTES, wsrc_base + (long)gt * WTILE_BYTES,
                     WTILE_BYTES, bar);
        }
    };

    issue_fill(0, 0);
    if (ntile > 1) issue_fill(1, 1);

    float acc[4][4];
#pragma unroll
    for (int a = 0; a < 4; a++)
#pragma unroll
        for (int b = 0; b < 4; b++) acc[a][b] = 0.f;

    const int arow = warp * 16 + (lane >> 2);
    const int sh   = (arow & 1) ? 2 : 0;
    const int kq   = lane & 3;

    for (int it = 0; it < ntile; it++) {
        const int buf = it & 1;
        mbar_wait(mb0 + 8 * buf, (uint32_t)((it >> 1) & 1));

        const float*    xb = (const float*)(smem + buf * STAGE_BYTES);
        const uint32_t* wb = (const uint32_t*)(smem + buf * STAGE_BYTES + XTILE_BYTES);
#pragma unroll
        for (int sub = 0; sub < 4; sub++) {
            const uint32_t* wbs = wb + sub * WSUB_WORDS;
            const int kb = sub * 32;
#pragma unroll
            for (int s = 0; s < 4; s++) {
                const int k8 = kb + s * 8;
                uint32_t a0 = __float_as_uint(xb[arow * XSTR2 + sh + k8 + kq]);
                uint32_t a1 = __float_as_uint(xb[(arow + 8) * XSTR2 + sh + k8 + kq]);
                uint32_t a2 = __float_as_uint(xb[arow * XSTR2 + sh + k8 + 4 + kq]);
                uint32_t a3 = __float_as_uint(xb[(arow + 8) * XSTR2 + sh + k8 + 4 + kq]);
                uint4 va = *(const uint4*)(wbs + s * 256 + lane * 4);
                uint4 vb = *(const uint4*)(wbs + s * 256 + 128 + lane * 4);
                const uint32_t* b0q = &va.x;
                const uint32_t* b1q = &vb.x;
#pragma unroll
                for (int nt = 0; nt < 4; nt++) {
                    asm volatile(
                        "mma.sync.aligned.m16n8k8.row.col.f32.tf32.tf32.f32 "
                        "{%0,%1,%2,%3}, {%4,%5,%6,%7}, {%8,%9}, {%0,%1,%2,%3};\n"
                        : "+f"(acc[nt][0]), "+f"(acc[nt][1]), "+f"(acc[nt][2]), "+f"(acc[nt][3])
                        : "r"(a0), "r"(a1), "r"(a2), "r"(a3), "r"(b0q[nt]), "r"(b1q[nt]));
                }
            }
        }
        __syncthreads();                    // all reads of buf done
        if (it + 2 < ntile) issue_fill(buf, it + 2);
    }

    // split-K epilogue: atomic accumulate
    const int r0 = m0 + arow;
    const int r1 = r0 + 8;
    const int c0 = (lane & 3) * 2;
#pragma unroll
    for (int nt = 0; nt < 4; nt++) {
        int c = nt * 8 + c0;
        if (r0 < NN) {
            atomicAdd(&d_h0[r0 * HD + c],     acc[nt][0]);
            atomicAdd(&d_h0[r0 * HD + c + 1], acc[nt][1]);
        }
        if (r1 < NN) {
            atomicAdd(&d_h0[r1 * HD + c],     acc[nt][2]);
            atomicAdd(&d_h0[r1 * HD + c + 1], acc[nt][3]);
        }
    }
}

// ---------------- scatter edges into CSR (packed (eid<<32)|src) --------------
__global__ void scatter_kernel(const int* __restrict__ ei, const float* __restrict__ ew) {
    int idx = blockIdx.x * 256 + threadIdx.x;
    if (idx >= TT * EE) return;
    int f = i64_flag(ei);
    int t = idx / EE, e = idx - t * EE;
    int i = ld_idx(ei, t * 2 * EE + e, f);
    int j = ld_idx(ei, t * 2 * EE + EE + e, f);
    int pos = atomicAdd(&d_cur[t * NN + j], 1);
    d_se[t * EE + pos] = ((unsigned long long)(unsigned)e << 32) | (unsigned)i;
    d_wb[t * EE + pos] = ew[idx];
}

// ---------------- dedup: warp-shuffle fast path (deg <= 32) ------------------
__global__ void __launch_bounds__(256) dedup_kernel() {
    int gw   = (blockIdx.x * 256 + threadIdx.x) >> 5;
    int lane = threadIdx.x & 31;
    if (gw >= TT * NN) return;
    int t = gw / NN, j = gw - t * NN;
    int beg = d_off[t * (NN + 1) + j];
    int end = d_off[t * (NN + 1) + j + 1];
    int deg = end - beg;

    float sum = 0.f;
    int selfw = 0;
    if (deg <= 32) {
        unsigned long long pk = 0; float w = 0.f; int active = (lane < deg);
        if (active) { pk = d_se[t * EE + beg + lane]; w = d_wb[t * EE + beg + lane]; }
        int win = active;
        for (int q = 0; q < deg; q++) {
            unsigned long long oq = __shfl_sync(0xffffffffu, pk, q);
            if (active && q != lane && (unsigned)oq == (unsigned)pk && oq > pk) win = 0;
        }
        if (active) {
            if (win) {
                sum = w;
                if ((int)(unsigned)pk == j) selfw = 1;
            } else {
                d_wb[t * EE + beg + lane] = 0.f;
            }
        }
    } else {
        for (int p = beg + lane; p < end; p += 32) {
            unsigned long long pk = d_se[t * EE + p];
            bool win = true;
            for (int q = beg; q < end; q++) {
                unsigned long long oq = d_se[t * EE + q];
                if (q != p && (unsigned)oq == (unsigned)pk && oq > pk) { win = false; break; }
            }
            if (win) {
                sum += d_wb[t * EE + p];
                if ((int)(unsigned)pk == j) selfw = 1;
            } else {
                d_wb[t * EE + p] = 0.f;
            }
        }
    }
#pragma unroll
    for (int o = 16; o; o >>= 1) {
        sum   += __shfl_xor_sync(0xffffffffu, sum, o);
        selfw |= __shfl_xor_sync(0xffffffffu, selfw, o);
    }
    if (lane == 0) {
        float diag = selfw ? 0.f : 1.f;
        d_diag[t * NN + j] = diag;
        d_dinv[t * NN + j] = rsqrtf(diag + sum);
    }
}

// ---------------- SpMM1 + ReLU + (h @ W2); stores g' = dinv_j * g ------------
__global__ void __launch_bounds__(256) spmm1_kernel(const float* __restrict__ b1,
                                                    const float* __restrict__ W2) {
    __shared__ float hs[8][HD];
    int gw   = (blockIdx.x * 256 + threadIdx.x) >> 5;
    int lane = threadIdx.x & 31;
    int wib  = (threadIdx.x >> 5);
    if (gw >= TT * NN) return;
    int t = gw / NN, j = gw - t * NN;
    const int tE = t * EE, tN = t * NN;
    int beg = d_off[t * (NN + 1) + j];
    int end = d_off[t * (NN + 1) + j + 1];

    float dj  = d_dinv[tN + j];
    float acc = d_diag[tN + j] * dj * d_h0[j * HD + lane];
    int p = beg;
    for (; p + 4 <= end; p += 4) {
        int s0 = (int)(unsigned)d_se[tE + p];
        int s1 = (int)(unsigned)d_se[tE + p + 1];
        int s2 = (int)(unsigned)d_se[tE + p + 2];
        int s3 = (int)(unsigned)d_se[tE + p + 3];
        float c0 = d_wb[tE + p]     * d_dinv[tN + s0];
        float c1 = d_wb[tE + p + 1] * d_dinv[tN + s1];
        float c2 = d_wb[tE + p + 2] * d_dinv[tN + s2];
        float c3 = d_wb[tE + p + 3] * d_dinv[tN + s3];
        float v0 = d_h0[s0 * HD + lane], v1 = d_h0[s1 * HD + lane];
        float v2 = d_h0[s2 * HD + lane], v3 = d_h0[s3 * HD + lane];
        acc = fmaf(c0, v0, acc); acc = fmaf(c1, v1, acc);
        acc = fmaf(c2, v2, acc); acc = fmaf(c3, v3, acc);
    }
    for (; p < end; p++) {
        int s = (int)(unsigned)d_se[tE + p];
        acc = fmaf(d_wb[tE + p] * d_dinv[tN + s], d_h0[s * HD + lane], acc);
    }
    float h = fmaxf(fmaf(acc, dj, b1[lane]), 0.f);
    hs[wib][lane] = h;
    __syncwarp();
    if (lane < ZD) {
        float s = 0.f;
#pragma unroll
        for (int c = 0; c < HD; c++) s = fmaf(hs[wib][c], W2[c * ZD + lane], s);
        d_g[(size_t)gw * ZD + lane] = s * dj;    // pre-scale by dinv_j
    }
}

// ---------------- SpMM2 + tanh (2 nodes/warp), g pre-scaled ------------------
__global__ void __launch_bounds__(256) spmm2_kernel(const float* __restrict__ b2,
                                                    float* __restrict__ out) {
    int gwarp = (blockIdx.x * 256 + threadIdx.x) >> 5;
    int lane  = threadIdx.x & 31;
    int half  = lane >> 4, k = lane & 15;
    int node  = gwarp * 2 + half;
    if (node >= TT * NN) return;
    int t = node / NN, j = node - t * NN;
    const int tE = t * EE, tN = t * NN;
    int beg = d_off[t * (NN + 1) + j];
    int end = d_off[t * (NN + 1) + j + 1];

    float dj  = d_dinv[tN + j];
    float acc = d_diag[tN + j] * d_g[(size_t)node * ZD + k];
    int p = beg;
    for (; p + 4 <= end; p += 4) {
        int s0 = (int)(unsigned)d_se[tE + p];
        int s1 = (int)(unsigned)d_se[tE + p + 1];
        int s2 = (int)(unsigned)d_se[tE + p + 2];
        int s3 = (int)(unsigned)d_se[tE + p + 3];
        float c0 = d_wb[tE + p],     c1 = d_wb[tE + p + 1];
        float c2 = d_wb[tE + p + 2], c3 = d_wb[tE + p + 3];
        float v0 = d_g[(size_t)(tN + s0) * ZD + k], v1 = d_g[(size_t)(tN + s1) * ZD + k];
        float v2 = d_g[(size_t)(tN + s2) * ZD + k], v3 = d_g[(size_t)(tN + s3) * ZD + k];
        acc = fmaf(c0, v0, acc); acc = fmaf(c1, v1, acc);
        acc = fmaf(c2, v2, acc); acc = fmaf(c3, v3, acc);
    }
    for (; p < end; p++) {
        int s = (int)(unsigned)d_se[tE + p];
        acc = fmaf(d_wb[tE + p], d_g[(size_t)(tN + s) * ZD + k], acc);
    }
    out[(size_t)node * ZD + k] = tanhf(fmaf(acc, dj, b2[k]));
}

// ---------------- launch (8 launches) -----------------------------------------
extern "C" void kernel_launch(void* const* d_in, const int* in_sizes, int n_in,
                              void* d_out, int out_size) {
    const float* x  = (const float*)d_in[0];
    const int*   ei = (const int*)d_in[1];
    const float* ew = (const float*)d_in[2];
    const float* W1 = (const float*)d_in[3];
    const float* b1 = (const float*)d_in[4];
    const float* W2 = (const float*)d_in[5];
    const float* b2 = (const float*)d_in[6];
    float* out = (float*)d_out;

    cudaFuncSetAttribute(gemm_kernel, cudaFuncAttributeMaxDynamicSharedMemorySize, GEMM_SMEM);

    prep_kernel<<<(PREP_TOT + 255) / 256, 256>>>(W1, x);              // 1
    hist_kernel<<<(TT * EE + 255) / 256, 256>>>(ei);                  // 2
    scan_kernel<<<dim3(SCH, TT), 1024>>>();                           // 3
    gemm_kernel<<<dim3(NTILE_TOT, KSPLIT), 256, GEMM_SMEM>>>(x);      // 4
    scatter_kernel<<<(TT * EE + 255) / 256, 256>>>(ei, ew);           // 5
    dedup_kernel<<<(TT * NN * 32 + 255) / 256, 256>>>();              // 6 (profiled)
    spmm1_kernel<<<(TT * NN * 32 + 255) / 256, 256>>>(b1, W2);        // 7
    spmm2_kernel<<<(TT * NN * 16 + 255) / 256, 256>>>(b2, out);       // 8
}

// round 17
// speedup vs baseline: 1.1143x; 1.0158x over previous
#include <cuda_runtime.h>
#include <cstdint>
#include <math.h>

#define NN 8746
#define KD 8746
#define HD 32
#define ZD 16
#define TT 6
#define EE 100000

// GEMM: BM=128, BK=128, split-K x2 (grid 138 = 1 block/SM), 2-stage TMA bulk
#define BMg 128
#define BKg 128
#define STg 2
#define KSPLIT 2
#define TPC 35
#define NTILE_TOT 69                     // ceil(8746/128)
#define KTAIL0 (68 * BKg)                // 8704; valid tail cols = 42
#define XSTR2 132                        // smem row stride in floats (528B)
#define XROWB2 (XSTR2 * 4)               // 528
#define XTILE_BYTES (BMg * XROWB2)       // 67584
#define WSUB_WORDS 1024                  // fragment-ordered 32-k sub-block
#define WTILE_BYTES (4 * WSUB_WORDS * 4) // 16384
#define STAGE_BYTES (XTILE_BYTES + WTILE_BYTES)  // 83968
#define GEMM_SMEM (STg * STAGE_BYTES)    // 167936

#define SCH 9

// ---------------- scratch (device globals; no allocations allowed) ----------
__device__ float    d_h0[NN * HD];
__device__ uint32_t d_w1t[(NTILE_TOT * 4) * WSUB_WORDS];
__device__ float    d_xtail[NN * XSTR2];
__device__ int      d_cnt[TT * NN];
__device__ int      d_off[TT * (NN + 1)];
__device__ int      d_cur[TT * NN];
__device__ uint4    d_sew[TT * EE];      // packed edge: {src, eid, w_bits, pad}
__device__ float    d_diag[TT * NN];
__device__ float    d_dinv[TT * NN];
__device__ float    d_g[TT * NN * ZD];   // stores dinv-prescaled g'

// ---------------- helpers ---------------------------------------------------
__device__ __forceinline__ uint32_t f2tf(float f) {
    uint32_t r;
    asm("cvt.rna.tf32.f32 %0, %1;" : "=r"(r) : "f"(f));
    return r;
}
__device__ __forceinline__ int ld_idx(const int* ei, int pos, int f) {
    return f ? ei[2 * pos] : ei[pos];
}
__device__ __forceinline__ int i64_flag(const int* ei) {
    return ((ei[1] | ei[3] | ei[5] | ei[7] | ei[9]) == 0) ? 1 : 0;
}
__device__ __forceinline__ uint32_t smem_u32(const void* p) {
    return (uint32_t)__cvta_generic_to_shared(p);
}
__device__ __forceinline__ void bulk_g2s(uint32_t dst, const void* src, int nb,
                                         uint32_t mbar) {
    asm volatile(
        "cp.async.bulk.shared::cta.global.mbarrier::complete_tx::bytes "
        "[%0], [%1], %2, [%3];\n"
        :: "r"(dst), "l"(src), "r"(nb), "r"(mbar) : "memory");
}
__device__ __forceinline__ void mbar_init(uint32_t mbar, uint32_t cnt) {
    asm volatile("mbarrier.init.shared.b64 [%0], %1;" :: "r"(mbar), "r"(cnt) : "memory");
}
__device__ __forceinline__ void mbar_expect(uint32_t mbar, uint32_t bytes) {
    asm volatile("mbarrier.arrive.expect_tx.shared.b64 _, [%0], %1;"
                 :: "r"(mbar), "r"(bytes) : "memory");
}
__device__ __forceinline__ void mbar_wait(uint32_t mbar, uint32_t parity) {
    uint32_t done;
    asm volatile(
        "{\n\t.reg .pred p;\n\t"
        "mbarrier.try_wait.parity.acquire.cta.shared::cta.b64 p, [%1], %2;\n\t"
        "selp.b32 %0, 1, 0, p;\n\t}"
        : "=r"(done) : "r"(mbar), "r"(parity) : "memory");
    if (!done) {
        asm volatile(
            "{\n\t.reg .pred P1;\n\t"
            "WL_%=:\n\t"
            "mbarrier.try_wait.parity.acquire.cta.shared::cta.b64 P1, [%0], %1, 0x989680;\n\t"
            "@P1 bra.uni WD_%=;\n\t"
            "bra.uni WL_%=;\n\t"
            "WD_%=:\n\t}"
            :: "r"(mbar), "r"(parity) : "memory");
    }
}

// ---------------- fused prep: h0/cnt zero + W1->tf32 + xtail staging ---------
#define PREP_H0 (NN * HD)
#define PREP_CNT (TT * NN)
#define PREP_W1 ((NTILE_TOT * 4) * WSUB_WORDS)
#define PREP_XT (NN * XSTR2)
#define PREP_TOT (PREP_H0 + PREP_CNT + PREP_W1 + PREP_XT)
__global__ void prep_kernel(const float* __restrict__ W1, const float* __restrict__ x) {
    int idx = blockIdx.x * 256 + threadIdx.x;
    if (idx < PREP_H0) {
        d_h0[idx] = 0.f;
    } else if (idx < PREP_H0 + PREP_CNT) {
        d_cnt[idx - PREP_H0] = 0;
    } else if (idx < PREP_H0 + PREP_CNT + PREP_W1) {
        int w = idx - PREP_H0 - PREP_CNT;
        int kt = w >> 10, r = w & 1023;
        int s = r >> 8, r2 = r & 255;
        int half = (r2 >> 7) & 1;
        int l = (r2 >> 2) & 31;
        int j = r2 & 3;
        int k = kt * 32 + s * 8 + (l & 3) + half * 4;
        int n = (l >> 2) + j * 8;
        d_w1t[w] = (k < KD) ? f2tf(W1[k * HD + n]) : 0u;
    } else if (idx < PREP_TOT) {
        int w = idx - PREP_H0 - PREP_CNT - PREP_W1;
        int r = w / XSTR2, c = w - r * XSTR2;
        int sh = (r & 1) * 2;
        int kc = c - sh;
        float v = (kc >= 0 && kc < KD - KTAIL0) ? x[(size_t)r * KD + KTAIL0 + kc] : 0.f;
        d_xtail[w] = v;
    }
}

// ---------------- edge histogram --------------------------------------------
__global__ void hist_kernel(const int* __restrict__ ei) {
    int idx = blockIdx.x * 256 + threadIdx.x;
    if (idx >= TT * EE) return;
    int f = i64_flag(ei);
    int t = idx / EE, e = idx - t * EE;
    int j = ld_idx(ei, t * 2 * EE + EE + e, f);
    atomicAdd(&d_cnt[t * NN + j], 1);
}

// ---------------- scan: redundant prefix -------------------------------------
__global__ void __launch_bounds__(1024) scan_kernel() {
    const int t   = blockIdx.y;
    const int ch  = blockIdx.x;
    const int tid = threadIdx.x;
    const int lane = tid & 31, w = tid >> 5;
    __shared__ int wsum[32];
    __shared__ int psum[32];

    int pre = 0;
    for (int i = tid; i < ch * 1024; i += 1024) pre += d_cnt[t * NN + i];

    int i = ch * 1024 + tid;
    int v = (i < NN) ? d_cnt[t * NN + i] : 0;

    int incl = v;
#pragma unroll
    for (int o = 1; o < 32; o <<= 1) {
        int u = __shfl_up_sync(0xffffffffu, incl, o);
        if (lane >= o) incl += u;
    }
#pragma unroll
    for (int o = 16; o; o >>= 1) pre += __shfl_xor_sync(0xffffffffu, pre, o);

    if (lane == 31) wsum[w] = incl;
    if (lane == 0)  psum[w] = pre;
    __syncthreads();
    if (w == 0) {
        int s = wsum[lane];
        int is = s;
#pragma unroll
        for (int o = 1; o < 32; o <<= 1) {
            int u = __shfl_up_sync(0xffffffffu, is, o);
            if (lane >= o) is += u;
        }
        wsum[lane] = is - s;
        int p = psum[lane];
#pragma unroll
        for (int o = 16; o; o >>= 1) p += __shfl_xor_sync(0xffffffffu, p, o);
        psum[lane] = p;
    }
    __syncthreads();

    int prev = psum[0];
    int blk_incl = wsum[w] + incl;

    if (i < NN) {
        int excl = prev + blk_incl - v;
        d_off[t * (NN + 1) + i] = excl;
        d_cur[t * NN + i]       = excl;
    }
    if (ch == SCH - 1 && tid == 1023)
        d_off[t * (NN + 1) + NN] = prev + blk_incl;
}

// ---------------- GEMM: h0 += x @ W1 (tf32 mma, BK=128 TMA bulk; R16 exact) --
__global__ void __launch_bounds__(256, 1)
gemm_kernel(const float* __restrict__ x) {
    extern __shared__ __align__(16) char smem[];
    __shared__ __align__(8) unsigned long long mbar_st[STg];

    const int tid  = threadIdx.x;
    const int lane = tid & 31;
    const int warp = tid >> 5;
    const int m0   = blockIdx.x * BMg;
    const int tile0 = blockIdx.y * TPC;
    const int ntile = min(TPC, NTILE_TOT - tile0);
    const int V     = min(BMg, NN - m0);
    const int evens = (V + 1) / 2, odds = V / 2;
    const uint32_t bytes_norm = (uint32_t)(evens * 512 + odds * 528 + WTILE_BYTES);
    const uint32_t bytes_tail = (uint32_t)(V * 528 + WTILE_BYTES);

    const uint32_t sbase = smem_u32(smem);
    const uint32_t mb0   = smem_u32(&mbar_st[0]);

    if (tid == 0) {
#pragma unroll
        for (int s = 0; s < STg; s++) mbar_init(mb0 + 8 * s, 1);
        asm volatile("fence.proxy.async.shared::cta;" ::: "memory");
    }
    __syncthreads();

    const int r = tid;
    const bool xrow = (tid < BMg) && (r < V);
    const int rodd = r & 1;
    const char* xsrc0 = (const char*)x
        + ((long)(m0 + r) * KD + (long)tile0 * BKg) * 4 - (rodd ? 8 : 0);
    const int xnb = rodd ? 528 : 512;
    const uint32_t xdst = (uint32_t)(r * XROWB2);
    const char* xtail_src = (const char*)d_xtail + (long)(m0 + r) * XROWB2;
    const bool wrow = (tid == 128);
    const char* wsrc_base = (const char*)d_w1t;

    auto issue_fill = [&](int buf, int tIdx) {
        const int gt = tile0 + tIdx;
        const uint32_t bar = mb0 + 8 * buf;
        const uint32_t sb  = sbase + (uint32_t)buf * STAGE_BYTES;
        if (tid == 0)
            mbar_expect(bar, (gt == NTILE_TOT - 1) ? bytes_tail : bytes_norm);
        if (xrow) {
            if (gt == NTILE_TOT - 1)
                bulk_g2s(sb + xdst, xtail_src, 528, bar);
            else
                bulk_g2s(sb + xdst, xsrc0 + (long)tIdx * (BKg * 4), xnb, bar);
        } else if (wrow) {
            bulk_g2s(sb + XTILE_BYTES, wsrc_base + (long)gt * WTILE_BYTES,
                     WTILE_BYTES, bar);
        }
    };

    issue_fill(0, 0);
    if (ntile > 1) issue_fill(1, 1);

    float acc[4][4];
#pragma unroll
    for (int a = 0; a < 4; a++)
#pragma unroll
        for (int b = 0; b < 4; b++) acc[a][b] = 0.f;

    const int arow = warp * 16 + (lane >> 2);
    const int sh   = (arow & 1) ? 2 : 0;
    const int kq   = lane & 3;

    for (int it = 0; it < ntile; it++) {
        const int buf = it & 1;
        mbar_wait(mb0 + 8 * buf, (uint32_t)((it >> 1) & 1));

        const float*    xb = (const float*)(smem + buf * STAGE_BYTES);
        const uint32_t* wb = (const uint32_t*)(smem + buf * STAGE_BYTES + XTILE_BYTES);
#pragma unroll
        for (int sub = 0; sub < 4; sub++) {
            const uint32_t* wbs = wb + sub * WSUB_WORDS;
            const int kb = sub * 32;
#pragma unroll
            for (int s = 0; s < 4; s++) {
                const int k8 = kb + s * 8;
                uint32_t a0 = __float_as_uint(xb[arow * XSTR2 + sh + k8 + kq]);
                uint32_t a1 = __float_as_uint(xb[(arow + 8) * XSTR2 + sh + k8 + kq]);
                uint32_t a2 = __float_as_uint(xb[arow * XSTR2 + sh + k8 + 4 + kq]);
                uint32_t a3 = __float_as_uint(xb[(arow + 8) * XSTR2 + sh + k8 + 4 + kq]);
                uint4 va = *(const uint4*)(wbs + s * 256 + lane * 4);
                uint4 vb = *(const uint4*)(wbs + s * 256 + 128 + lane * 4);
                const uint32_t* b0q = &va.x;
                const uint32_t* b1q = &vb.x;
#pragma unroll
                for (int nt = 0; nt < 4; nt++) {
                    asm volatile(
                        "mma.sync.aligned.m16n8k8.row.col.f32.tf32.tf32.f32 "
                        "{%0,%1,%2,%3}, {%4,%5,%6,%7}, {%8,%9}, {%0,%1,%2,%3};\n"
                        : "+f"(acc[nt][0]), "+f"(acc[nt][1]), "+f"(acc[nt][2]), "+f"(acc[nt][3])
                        : "r"(a0), "r"(a1), "r"(a2), "r"(a3), "r"(b0q[nt]), "r"(b1q[nt]));
                }
            }
        }
        __syncthreads();
        if (it + 2 < ntile) issue_fill(buf, it + 2);
    }

    const int r0 = m0 + arow;
    const int r1 = r0 + 8;
    const int c0 = (lane & 3) * 2;
#pragma unroll
    for (int nt = 0; nt < 4; nt++) {
        int c = nt * 8 + c0;
        if (r0 < NN) {
            atomicAdd(&d_h0[r0 * HD + c],     acc[nt][0]);
            atomicAdd(&d_h0[r0 * HD + c + 1], acc[nt][1]);
        }
        if (r1 < NN) {
            atomicAdd(&d_h0[r1 * HD + c],     acc[nt][2]);
            atomicAdd(&d_h0[r1 * HD + c + 1], acc[nt][3]);
        }
    }
}

// ---------------- scatter edges into CSR (single 16B store per edge) ---------
__global__ void scatter_kernel(const int* __restrict__ ei, const float* __restrict__ ew) {
    int idx = blockIdx.x * 256 + threadIdx.x;
    if (idx >= TT * EE) return;
    int f = i64_flag(ei);
    int t = idx / EE, e = idx - t * EE;
    int i = ld_idx(ei, t * 2 * EE + e, f);
    int j = ld_idx(ei, t * 2 * EE + EE + e, f);
    int pos = atomicAdd(&d_cur[t * NN + j], 1);
    uint4 pk;
    pk.x = (unsigned)i;
    pk.y = (unsigned)e;
    pk.z = __float_as_uint(ew[idx]);
    pk.w = 0u;
    d_sew[t * EE + pos] = pk;
}

// ---------------- dedup: warp-shuffle fast path (deg <= 32) ------------------
__global__ void __launch_bounds__(256) dedup_kernel() {
    int gw   = (blockIdx.x * 256 + threadIdx.x) >> 5;
    int lane = threadIdx.x & 31;
    if (gw >= TT * NN) return;
    int t = gw / NN, j = gw - t * NN;
    int beg = d_off[t * (NN + 1) + j];
    int end = d_off[t * (NN + 1) + j + 1];
    int deg = end - beg;

    float sum = 0.f;
    int selfw = 0;
    if (deg <= 32) {
        unsigned long long pk = 0; float w = 0.f; int active = (lane < deg);
        if (active) {
            uint4 q = d_sew[t * EE + beg + lane];
            pk = ((unsigned long long)q.y << 32) | q.x;
            w  = __uint_as_float(q.z);
        }
        int win = active;
        for (int q = 0; q < deg; q++) {
            unsigned long long oq = __shfl_sync(0xffffffffu, pk, q);
            if (active && q != lane && (unsigned)oq == (unsigned)pk && oq > pk) win = 0;
        }
        if (active) {
            if (win) {
                sum = w;
                if ((int)(unsigned)pk == j) selfw = 1;
            } else {
                ((uint32_t*)d_sew)[(size_t)(t * EE + beg + lane) * 4 + 2] = 0u; // w=0
            }
        }
    } else {
        for (int p = beg + lane; p < end; p += 32) {
            uint4 qv = d_sew[t * EE + p];
            unsigned long long pk = ((unsigned long long)qv.y << 32) | qv.x;
            bool win = true;
            for (int q = beg; q < end; q++) {
                uint4 ov = d_sew[t * EE + q];
                unsigned long long oq = ((unsigned long long)ov.y << 32) | ov.x;
                if (q != p && (unsigned)oq == (unsigned)pk && oq > pk) { win = false; break; }
            }
            if (win) {
                sum += __uint_as_float(qv.z);
                if ((int)qv.x == j) selfw = 1;
            } else {
                ((uint32_t*)d_sew)[(size_t)(t * EE + p) * 4 + 2] = 0u;
            }
        }
    }
#pragma unroll
    for (int o = 16; o; o >>= 1) {
        sum   += __shfl_xor_sync(0xffffffffu, sum, o);
        selfw |= __shfl_xor_sync(0xffffffffu, selfw, o);
    }
    if (lane == 0) {
        float diag = selfw ? 0.f : 1.f;
        d_diag[t * NN + j] = diag;
        d_dinv[t * NN + j] = rsqrtf(diag + sum);
    }
}

// ---------------- SpMM1 + ReLU + (h @ W2); stores g' = dinv_j * g ------------
__global__ void __launch_bounds__(256) spmm1_kernel(const float* __restrict__ b1,
                                                    const float* __restrict__ W2) {
    __shared__ float hs[8][HD];
    int gw   = (blockIdx.x * 256 + threadIdx.x) >> 5;
    int lane = threadIdx.x & 31;
    int wib  = (threadIdx.x >> 5);
    if (gw >= TT * NN) return;
    int t = gw / NN, j = gw - t * NN;
    const int tE = t * EE, tN = t * NN;
    int beg = d_off[t * (NN + 1) + j];
    int end = d_off[t * (NN + 1) + j + 1];

    float dj  = d_dinv[tN + j];
    float acc = d_diag[tN + j] * dj * d_h0[j * HD + lane];
    int p = beg;
    for (; p + 4 <= end; p += 4) {
        uint4 q0 = d_sew[tE + p],     q1 = d_sew[tE + p + 1];
        uint4 q2 = d_sew[tE + p + 2], q3 = d_sew[tE + p + 3];
        int s0 = (int)q0.x, s1 = (int)q1.x, s2 = (int)q2.x, s3 = (int)q3.x;
        float c0 = __uint_as_float(q0.z) * d_dinv[tN + s0];
        float c1 = __uint_as_float(q1.z) * d_dinv[tN + s1];
        float c2 = __uint_as_float(q2.z) * d_dinv[tN + s2];
        float c3 = __uint_as_float(q3.z) * d_dinv[tN + s3];
        float v0 = d_h0[s0 * HD + lane], v1 = d_h0[s1 * HD + lane];
        float v2 = d_h0[s2 * HD + lane], v3 = d_h0[s3 * HD + lane];
        acc = fmaf(c0, v0, acc); acc = fmaf(c1, v1, acc);
        acc = fmaf(c2, v2, acc); acc = fmaf(c3, v3, acc);
    }
    for (; p < end; p++) {
        uint4 q = d_sew[tE + p];
        int s = (int)q.x;
        acc = fmaf(__uint_as_float(q.z) * d_dinv[tN + s], d_h0[s * HD + lane], acc);
    }
    float h = fmaxf(fmaf(acc, dj, b1[lane]), 0.f);
    hs[wib][lane] = h;
    __syncwarp();
    if (lane < ZD) {
        float s = 0.f;
#pragma unroll
        for (int c = 0; c < HD; c++) s = fmaf(hs[wib][c], W2[c * ZD + lane], s);
        d_g[(size_t)gw * ZD + lane] = s * dj;
    }
}

// ---------------- SpMM2 + tanh (2 nodes/warp), g pre-scaled ------------------
__global__ void __launch_bounds__(256) spmm2_kernel(const float* __restrict__ b2,
                                                    float* __restrict__ out) {
    int gwarp = (blockIdx.x * 256 + threadIdx.x) >> 5;
    int lane  = threadIdx.x & 31;
    int half  = lane >> 4, k = lane & 15;
    int node  = gwarp * 2 + half;
    if (node >= TT * NN) return;
    int t = node / NN, j = node - t * NN;
    const int tE = t * EE, tN = t * NN;
    int beg = d_off[t * (NN + 1) + j];
    int end = d_off[t * (NN + 1) + j + 1];

    float dj  = d_dinv[tN + j];
    float acc = d_diag[tN + j] * d_g[(size_t)node * ZD + k];
    int p = beg;
    for (; p + 4 <= end; p += 4) {
        uint4 q0 = d_sew[tE + p],     q1 = d_sew[tE + p + 1];
        uint4 q2 = d_sew[tE + p + 2], q3 = d_sew[tE + p + 3];
        int s0 = (int)q0.x, s1 = (int)q1.x, s2 = (int)q2.x, s3 = (int)q3.x;
        float c0 = __uint_as_float(q0.z), c1 = __uint_as_float(q1.z);
        float c2 = __uint_as_float(q2.z), c3 = __uint_as_float(q3.z);
        float v0 = d_g[(size_t)(tN + s0) * ZD + k], v1 = d_g[(size_t)(tN + s1) * ZD + k];
        float v2 = d_g[(size_t)(tN + s2) * ZD + k], v3 = d_g[(size_t)(tN + s3) * ZD + k];
        acc = fmaf(c0, v0, acc); acc = fmaf(c1, v1, acc);
        acc = fmaf(c2, v2, acc); acc = fmaf(c3, v3, acc);
    }
    for (; p < end; p++) {
        uint4 q = d_sew[tE + p];
        acc = fmaf(__uint_as_float(q.z), d_g[(size_t)(tN + (int)q.x) * ZD + k], acc);
    }
    out[(size_t)node * ZD + k] = tanhf(fmaf(acc, dj, b2[k]));
}

// ---------------- launch (8 launches) -----------------------------------------
extern "C" void kernel_launch(void* const* d_in, const int* in_sizes, int n_in,
                              void* d_out, int out_size) {
    const float* x  = (const float*)d_in[0];
    const int*   ei = (const int*)d_in[1];
    const float* ew = (const float*)d_in[2];
    const float* W1 = (const float*)d_in[3];
    const float* b1 = (const float*)d_in[4];
    const float* W2 = (const float*)d_in[5];
    const float* b2 = (const float*)d_in[6];
    float* out = (float*)d_out;

    cudaFuncSetAttribute(gemm_kernel, cudaFuncAttributeMaxDynamicSharedMemorySize, GEMM_SMEM);

    prep_kernel<<<(PREP_TOT + 255) / 256, 256>>>(W1, x);              // 1
    hist_kernel<<<(TT * EE + 255) / 256, 256>>>(ei);                  // 2
    scan_kernel<<<dim3(SCH, TT), 1024>>>();                           // 3
    gemm_kernel<<<dim3(NTILE_TOT, KSPLIT), 256, GEMM_SMEM>>>(x);      // 4
    scatter_kernel<<<(TT * EE + 255) / 256, 256>>>(ei, ew);           // 5
    dedup_kernel<<<(TT * NN * 32 + 255) / 256, 256>>>();              // 6 (profiled)
    spmm1_kernel<<<(TT * NN * 32 + 255) / 256, 256>>>(b1, W2);        // 7
    spmm2_kernel<<<(TT * NN * 16 + 255) / 256, 256>>>(b2, out);       // 8
}